// round 14
// baseline (speedup 1.0000x reference)
#include <cuda_runtime.h>
#include <math.h>

#define B_   32
#define L_   512
#define H_   768
#define T_   8
#define DK_  96
#define BT_  256
#define LL_  (512*512)

// ---------------- f32x2 packed helpers ----------------
__device__ __forceinline__ unsigned long long pk2(float x, float y) {
    unsigned long long r;
    asm("mov.b64 %0, {%1, %2};" : "=l"(r) : "f"(x), "f"(y));
    return r;
}
__device__ __forceinline__ float2 unpk(unsigned long long v) {
    float2 f;
    asm("mov.b64 {%0, %1}, %2;" : "=f"(f.x), "=f"(f.y) : "l"(v));
    return f;
}
#define FMA2(d, a, b) asm("fma.rn.f32x2 %0, %1, %2, %0;" : "+l"(d) : "l"(a), "l"(b))

// ---------------- tf32 helpers ----------------
__device__ __forceinline__ unsigned cvt_tf32(float x) {
    unsigned u;
    asm("cvt.rna.tf32.f32 %0, %1;" : "=r"(u) : "f"(x));
    return u;
}
#define MMA_TF32(c, a, b) \
    asm("mma.sync.aligned.m16n8k8.row.col.f32.tf32.tf32.f32 " \
        "{%0,%1,%2,%3},{%4,%5,%6,%7},{%8,%9},{%0,%1,%2,%3};" \
        : "+f"((c)[0]), "+f"((c)[1]), "+f"((c)[2]), "+f"((c)[3]) \
        : "r"((a)[0]), "r"((a)[1]), "r"((a)[2]), "r"((a)[3]), \
          "r"((b)[0]), "r"((b)[1]))

// ---------------- scratch ----------------
__device__ float g_Q[16384 * 768];
__device__ float g_K[16384 * 768];
__device__ float g_A[(size_t)BT_ * LL_];
__device__ float g_W[(size_t)BT_ * LL_];
__device__ float g_f[BT_ * 512];
__device__ float g_deg[BT_ * 512];
__device__ float g_diag[BT_ * 512];

// ================= K1: Q = X@Wq^T+bq ; K = X@Wk^T+bk (tf32 MMA) =================
__global__ __launch_bounds__(256) void proj_kernel(
    const float* __restrict__ X,
    const float* __restrict__ Wq, const float* __restrict__ bq,
    const float* __restrict__ Wk, const float* __restrict__ bk)
{
    __shared__ unsigned As[128 * 36];
    __shared__ unsigned Bs[128 * 36];
    const int z = blockIdx.z;
    const float* Wm   = z ? Wk : Wq;
    const float* bias = z ? bk : bq;
    float*       Out  = z ? g_K : g_Q;
    const int bm = blockIdx.y, bn = blockIdx.x;
    const int tid = threadIdx.x;
    const int warp = tid >> 5, lane = tid & 31;
    const int wm = warp >> 2, wn = warp & 3;
    const int grp = lane >> 2, tig = lane & 3;

    float acc[4][4][4];
#pragma unroll
    for (int i = 0; i < 4; i++)
#pragma unroll
        for (int j = 0; j < 4; j++)
#pragma unroll
            for (int k = 0; k < 4; k++) acc[i][j][k] = 0.f;

    const int r  = tid >> 1;
    const int kp = (tid & 1) * 16;
    const float* Ag = X  + (size_t)(bm * 128 + r) * H_ + kp;
    const float* Bg = Wm + (size_t)(bn * 128 + r) * H_ + kp;
    unsigned* Asw = As + r * 36 + kp;
    unsigned* Bsw = Bs + r * 36 + kp;

    for (int c0 = 0; c0 < H_; c0 += 32) {
#pragma unroll
        for (int v = 0; v < 4; v++) {
            float4 a4 = *(const float4*)(Ag + c0 + v * 4);
            float4 b4 = *(const float4*)(Bg + c0 + v * 4);
            uint4 ua = make_uint4(cvt_tf32(a4.x), cvt_tf32(a4.y), cvt_tf32(a4.z), cvt_tf32(a4.w));
            uint4 ub = make_uint4(cvt_tf32(b4.x), cvt_tf32(b4.y), cvt_tf32(b4.z), cvt_tf32(b4.w));
            *(uint4*)(Asw + v * 4) = ua;
            *(uint4*)(Bsw + v * 4) = ub;
        }
        __syncthreads();
#pragma unroll
        for (int ks = 0; ks < 4; ks++) {
            const int kb = ks * 8;
            unsigned a[4][4], b[4][2];
#pragma unroll
            for (int mi = 0; mi < 4; mi++) {
                const int base = (wm * 64 + mi * 16) * 36 + kb;
                a[mi][0] = As[base + grp * 36 + tig];
                a[mi][1] = As[base + (grp + 8) * 36 + tig];
                a[mi][2] = As[base + grp * 36 + tig + 4];
                a[mi][3] = As[base + (grp + 8) * 36 + tig + 4];
            }
#pragma unroll
            for (int ni = 0; ni < 4; ni++) {
                const int nbase = (wn * 32 + ni * 8 + grp) * 36 + kb;
                b[ni][0] = Bs[nbase + tig];
                b[ni][1] = Bs[nbase + tig + 4];
            }
#pragma unroll
            for (int mi = 0; mi < 4; mi++)
#pragma unroll
                for (int ni = 0; ni < 4; ni++)
                    MMA_TF32(acc[mi][ni], a[mi], b[ni]);
        }
        __syncthreads();
    }
#pragma unroll
    for (int mi = 0; mi < 4; mi++) {
        const int row = bm * 128 + wm * 64 + mi * 16 + grp;
#pragma unroll
        for (int ni = 0; ni < 4; ni++) {
            const int col = bn * 128 + wn * 32 + ni * 8 + 2 * tig;
            float2 bb = *(const float2*)(bias + col);
            float2 o0 = make_float2(acc[mi][ni][0] + bb.x, acc[mi][ni][1] + bb.y);
            float2 o1 = make_float2(acc[mi][ni][2] + bb.x, acc[mi][ni][3] + bb.y);
            *(float2*)(Out + (size_t)row * H_ + col)       = o0;
            *(float2*)(Out + (size_t)(row + 8) * H_ + col) = o1;
        }
    }
}

// ================= K2: scores -> g_A (tf32 MMA, scaled + masked) =================
__global__ __launch_bounds__(256) void scores_kernel(const int* __restrict__ mask)
{
    __shared__ unsigned As[128 * 36];
    __shared__ unsigned Bs[128 * 36];
    const int bt = blockIdx.z;
    const int b = bt >> 3, t = bt & 7;
    const int bm = blockIdx.y, bn = blockIdx.x;
    const int tid = threadIdx.x;
    const int warp = tid >> 5, lane = tid & 31;
    const int wm = warp >> 2, wn = warp & 3;
    const int grp = lane >> 2, tig = lane & 3;

    float acc[4][4][4];
#pragma unroll
    for (int i = 0; i < 4; i++)
#pragma unroll
        for (int j = 0; j < 4; j++)
#pragma unroll
            for (int k = 0; k < 4; k++) acc[i][j][k] = 0.f;

    const int r  = tid >> 1;
    const int kp = (tid & 1) * 16;
    const float* Ag = g_Q + (size_t)(b * 512 + bm * 128 + r) * H_ + t * DK_ + kp;
    const float* Bg = g_K + (size_t)(b * 512 + bn * 128 + r) * H_ + t * DK_ + kp;
    unsigned* Asw = As + r * 36 + kp;
    unsigned* Bsw = Bs + r * 36 + kp;

    for (int c0 = 0; c0 < DK_; c0 += 32) {
#pragma unroll
        for (int v = 0; v < 4; v++) {
            float4 a4 = *(const float4*)(Ag + c0 + v * 4);
            float4 b4 = *(const float4*)(Bg + c0 + v * 4);
            uint4 ua = make_uint4(cvt_tf32(a4.x), cvt_tf32(a4.y), cvt_tf32(a4.z), cvt_tf32(a4.w));
            uint4 ub = make_uint4(cvt_tf32(b4.x), cvt_tf32(b4.y), cvt_tf32(b4.z), cvt_tf32(b4.w));
            *(uint4*)(Asw + v * 4) = ua;
            *(uint4*)(Bsw + v * 4) = ub;
        }
        __syncthreads();
#pragma unroll
        for (int ks = 0; ks < 4; ks++) {
            const int kb = ks * 8;
            unsigned a[4][4], bfr[4][2];
#pragma unroll
            for (int mi = 0; mi < 4; mi++) {
                const int base = (wm * 64 + mi * 16) * 36 + kb;
                a[mi][0] = As[base + grp * 36 + tig];
                a[mi][1] = As[base + (grp + 8) * 36 + tig];
                a[mi][2] = As[base + grp * 36 + tig + 4];
                a[mi][3] = As[base + (grp + 8) * 36 + tig + 4];
            }
#pragma unroll
            for (int ni = 0; ni < 4; ni++) {
                const int nbase = (wn * 32 + ni * 8 + grp) * 36 + kb;
                bfr[ni][0] = Bs[nbase + tig];
                bfr[ni][1] = Bs[nbase + tig + 4];
            }
#pragma unroll
            for (int mi = 0; mi < 4; mi++)
#pragma unroll
                for (int ni = 0; ni < 4; ni++)
                    MMA_TF32(acc[mi][ni], a[mi], bfr[ni]);
        }
        __syncthreads();
    }
    const float scale = 0.10206207261596575f;
    float* Om = g_A + (size_t)bt * LL_;
#pragma unroll
    for (int mi = 0; mi < 4; mi++) {
        const int row = bm * 128 + wm * 64 + mi * 16 + grp;
#pragma unroll
        for (int ni = 0; ni < 4; ni++) {
            const int col = bn * 128 + wn * 32 + ni * 8 + 2 * tig;
            int2 mv = *(const int2*)(mask + b * 512 + col);
            float2 o0 = make_float2(
                mv.x ? acc[mi][ni][0] * scale : -1000000000.0f,
                mv.y ? acc[mi][ni][1] * scale : -1000000000.0f);
            float2 o1 = make_float2(
                mv.x ? acc[mi][ni][2] * scale : -1000000000.0f,
                mv.y ? acc[mi][ni][3] * scale : -1000000000.0f);
            *(float2*)(Om + (size_t)row * 512 + col)       = o0;
            *(float2*)(Om + (size_t)(row + 8) * 512 + col) = o1;
        }
    }
}

// ========== K3: per row: A = exp(softmax(s)), zero diagonal (in place) ==========
__global__ __launch_bounds__(256) void softmax_kernel()
{
    const int row = blockIdx.x;
    const int q = row & 511;
    float* r = g_A + (size_t)row * 512;
    const int tid = threadIdx.x;
    float v0 = r[tid], v1 = r[tid + 256];

    __shared__ float red[16];
    float m = fmaxf(v0, v1);
#pragma unroll
    for (int o = 16; o; o >>= 1) m = fmaxf(m, __shfl_xor_sync(0xffffffffu, m, o));
    if ((tid & 31) == 0) red[tid >> 5] = m;
    __syncthreads();
    m = fmaxf(fmaxf(fmaxf(red[0], red[1]), fmaxf(red[2], red[3])),
              fmaxf(fmaxf(red[4], red[5]), fmaxf(red[6], red[7])));

    float e0 = expf(v0 - m), e1 = expf(v1 - m);
    float s = e0 + e1;
#pragma unroll
    for (int o = 16; o; o >>= 1) s += __shfl_xor_sync(0xffffffffu, s, o);
    if ((tid & 31) == 0) red[8 + (tid >> 5)] = s;
    __syncthreads();
    s = ((red[8] + red[9]) + (red[10] + red[11])) +
        ((red[12] + red[13]) + (red[14] + red[15]));
    const float inv = 1.0f / s;

    float a0 = expf(e0 * inv); if (tid == q)       a0 = 0.f;
    float a1 = expf(e1 * inv); if (tid + 256 == q) a1 = 0.f;
    r[tid] = a0; r[tid + 256] = a1;
}

// ================= K4: f[bt][l] = x[b,l,:].Wroot[t,:] + broot[t] =================
__global__ __launch_bounds__(256) void f_kernel(const float* __restrict__ x,
                                                const float* __restrict__ Wroot,
                                                const float* __restrict__ broot)
{
    __shared__ float sW[T_ * H_];
    for (int idx = threadIdx.x; idx < T_ * H_; idx += 256) sW[idx] = Wroot[idx];
    __syncthreads();
    const int w = threadIdx.x >> 5, lane = threadIdx.x & 31;
    const int bl = blockIdx.x * 8 + w;
    const int b = bl >> 9, l = bl & 511;
    const float* xr = x + (size_t)bl * H_;
    float xv[24];
#pragma unroll
    for (int i = 0; i < 24; i++) xv[i] = xr[lane + i * 32];
#pragma unroll
    for (int t = 0; t < T_; t++) {
        float s = 0.f;
#pragma unroll
        for (int i = 0; i < 24; i++) s += xv[i] * sW[t * H_ + lane + i * 32];
#pragma unroll
        for (int o = 16; o; o >>= 1) s += __shfl_xor_sync(0xffffffffu, s, o);
        if (lane == 0) g_f[(b * T_ + t) * 512 + l] = s + broot[t];
    }
}

// ================= K5: deg[bt][k] = sum_q A[bt][q][k] =================
__global__ __launch_bounds__(512) void deg_kernel()
{
    const int bt = blockIdx.x, k = threadIdx.x;
    const float* Am = g_A + (size_t)bt * LL_ + k;
    float s0 = 0, s1 = 0, s2 = 0, s3 = 0;
    for (int q = 0; q < 512; q += 4) {
        s0 += Am[(size_t)q * 512];
        s1 += Am[(size_t)(q + 1) * 512];
        s2 += Am[(size_t)(q + 2) * 512];
        s3 += Am[(size_t)(q + 3) * 512];
    }
    g_deg[bt * 512 + k] = (s0 + s1) + (s2 + s3);
}

// ===== K6: permuted Lbar: W[i][j] = Lbar[(i+1)&511][(j+1)&511] =====
__global__ __launch_bounds__(512) void build_kernel()
{
    const int i = blockIdx.x, bt = blockIdx.y, j = threadIdx.x;
    const int pi = (i + 1) & 511, pj = (j + 1) & 511;
    float v;
    if (pi == 0) {
        v = g_f[bt * 512 + pj];
    } else {
        v = -g_A[(size_t)bt * LL_ + (size_t)pi * 512 + pj];
        if (pi == pj) v += g_deg[bt * 512 + pj];
    }
    g_W[(size_t)bt * LL_ + (size_t)i * 512 + j] = v;
}

// ===== K7: blocked Gauss-Jordan inverse (nb=64, no pivoting, all-fp32 FFMA2) =====
// Phase C double-buffered Ct + L2 prefetch of epilogue RMW lines.
// smem floats: sRP[64*512]=32768, sG[64*72]=4608, sCt0/sCt1[64*68]=4352 each,
//              sck[64], srk[64]
#define IV_RP  0
#define IV_G   32768
#define IV_CT0 (32768 + 4608)
#define IV_CT1 (32768 + 4608 + 4352)
#define IV_CK  (32768 + 4608 + 4352 + 4352)
#define IV_RK  (32768 + 4608 + 4352 + 4352 + 64)
#define SMEM_INV_FLOATS (32768 + 4608 + 4352 + 4352 + 128)
#define SMEM_INV_BYTES (SMEM_INV_FLOATS * 4)

__global__ __launch_bounds__(512) void invert_kernel()
{
    extern __shared__ float sm[];
    float* sRP  = sm + IV_RP;
    float* sG   = sm + IV_G;
    float* sCt0 = sm + IV_CT0;
    float* sCt1 = sm + IV_CT1;
    float* sck  = sm + IV_CK;
    float* srk  = sm + IV_RK;
    float* M = g_W + (size_t)blockIdx.x * LL_;
    const int tid = threadIdx.x;
    const int tx = tid & 63, ty = tid >> 6;
    const int c0 = tx * 4;
    const int ty8 = ty * 8;

    for (int s = 0; s < 8; s++) {
        const int k0 = s * 64;

        // ---- Phase A: load G = D^T, invert via GJ (G becomes (D^-1)^T) ----
        for (int idx = tid; idx < 4096; idx += 512) {
            int bb = idx >> 6, aa = idx & 63;
            sG[aa * 72 + bb] = M[(size_t)(k0 + bb) * 512 + k0 + aa];
        }
        __syncthreads();
        for (int k = 0; k < 64; k++) {
            if (tid < 64) { sck[tid] = sG[tid * 72 + k]; srk[tid] = sG[k * 72 + tid]; }
            __syncthreads();
            const float p = 1.0f / srk[k];
            for (int idx = tid; idx < 4096; idx += 512) {
                int i2 = idx >> 6, j2 = idx & 63;
                float v;
                if (i2 == k)      v = (j2 == k) ? p : srk[j2] * p;
                else if (j2 == k) v = -sck[i2] * p;
                else              v = sG[i2 * 72 + j2] - sck[i2] * (srk[j2] * p);
                sG[i2 * 72 + j2] = v;
            }
            __syncthreads();
        }

        // ---- Phase B: pivot rows S = Dinv*OldRows (FFMA2); write M + sRP ----
        {
            const int c = tid;
            const bool piv = (c >= k0) && (c < k0 + 64);
            const int cc = c - k0;
            unsigned long long acc2[32];
#pragma unroll
            for (int m = 0; m < 32; m++) acc2[m] = 0ull;
#pragma unroll 4
            for (int k = 0; k < 64; k++) {
                float rk = M[(size_t)(k0 + k) * 512 + c];
                unsigned long long ak = pk2(rk, rk);
                const ulonglong2* gp = (const ulonglong2*)&sG[k * 72];
#pragma unroll
                for (int m = 0; m < 16; m++) {
                    ulonglong2 g2 = gp[m];
                    FMA2(acc2[2 * m],     ak, g2.x);
                    FMA2(acc2[2 * m + 1], ak, g2.y);
                }
            }
#pragma unroll
            for (int m = 0; m < 32; m++) {
                float2 v = unpk(acc2[m]);
                int r0 = 2 * m, r1 = 2 * m + 1;
                float a0 = piv ? sG[cc * 72 + r0] : v.x;
                float a1 = piv ? sG[cc * 72 + r1] : v.y;
                sRP[r0 * 512 + c] = a0;
                sRP[r1 * 512 + c] = a1;
                M[(size_t)(k0 + r0) * 512 + c] = a0;
                M[(size_t)(k0 + r1) * 512 + c] = a1;
            }
        }
        __syncthreads();

        // ---- preload first rb's Ct into buffer 0 ----
        {
            const int rb0 = (s == 0) ? 1 : 0;
            const int nrow0 = rb0 * 64;
#pragma unroll
            for (int t = 0; t < 8; t++) {
                int idx = tid + t * 512;
                int rr = idx >> 6, k = idx & 63;
                sCt0[k * 68 + rr] = M[(size_t)(nrow0 + rr) * 512 + k0 + k];
            }
        }
        __syncthreads();

        // ---- Phase C: trailing update (FFMA2 8x8), double-buffered Ct ----
        int buf = 0;
        for (int ii = 0; ii < 7; ii++) {
            const int rb  = ii + (ii >= s ? 1 : 0);
            const int nn  = ii + 1;
            const int nxt = (nn < 7) ? (nn + (nn >= s ? 1 : 0)) : -1;
            const int row0 = rb * 64;
            float* sCtc = buf ? sCt1 : sCt0;
            float* sCtn = buf ? sCt0 : sCt1;

            // prefetch next rb's Ct into registers (hidden under compute)
            float pf[8];
            if (nxt >= 0) {
                const int nrow0 = nxt * 64;
#pragma unroll
                for (int t = 0; t < 8; t++) {
                    int idx = tid + t * 512;
                    int rr = idx >> 6, k = idx & 63;
                    pf[t] = M[(size_t)(nrow0 + rr) * 512 + k0 + k];
                }
            }
            // L2 prefetch of the epilogue RMW lines (one thread per 128B line)
            if ((tx & 7) == 0) {
#pragma unroll
                for (int i = 0; i < 8; i++) {
                    const float* p0 = &M[(size_t)(row0 + ty8 + i) * 512 + c0];
                    asm volatile("prefetch.global.L2 [%0];" :: "l"(p0));
                    asm volatile("prefetch.global.L2 [%0];" :: "l"(p0 + 256));
                }
            }

            unsigned long long acc2[8][4];
#pragma unroll
            for (int i = 0; i < 8; i++)
#pragma unroll
                for (int j = 0; j < 4; j++) acc2[i][j] = 0ull;

#pragma unroll 4
            for (int k = 0; k < 64; k++) {
                float a[8];
                *(float4*)(a)     = *(const float4*)&sCtc[k * 68 + ty8];
                *(float4*)(a + 4) = *(const float4*)&sCtc[k * 68 + ty8 + 4];
                ulonglong2 b0 = *(const ulonglong2*)&sRP[k * 512 + c0];
                ulonglong2 b1 = *(const ulonglong2*)&sRP[k * 512 + c0 + 256];
#pragma unroll
                for (int i = 0; i < 8; i++) {
                    unsigned long long aa = pk2(a[i], a[i]);
                    FMA2(acc2[i][0], aa, b0.x);
                    FMA2(acc2[i][1], aa, b0.y);
                    FMA2(acc2[i][2], aa, b1.x);
                    FMA2(acc2[i][3], aa, b1.y);
                }
            }

            const bool pivA = (c0 >= k0) && (c0 < k0 + 64);
            const bool pivB = (c0 + 256 >= k0) && (c0 + 256 < k0 + 64);
#pragma unroll
            for (int i = 0; i < 8; i++) {
                const int rr = ty8 + i;
                const int r = row0 + rr;
                float2 v0 = unpk(acc2[i][0]), v1 = unpk(acc2[i][1]);
                float2 v2 = unpk(acc2[i][2]), v3 = unpk(acc2[i][3]);
                float4 o0 = *(const float4*)&M[(size_t)r * 512 + c0];
                o0.x -= v0.x; o0.y -= v0.y; o0.z -= v1.x; o0.w -= v1.y;
                if (pivA) {
                    int cb = c0 - k0;
                    o0.x -= sCtc[(cb + 0) * 68 + rr];
                    o0.y -= sCtc[(cb + 1) * 68 + rr];
                    o0.z -= sCtc[(cb + 2) * 68 + rr];
                    o0.w -= sCtc[(cb + 3) * 68 + rr];
                }
                *(float4*)&M[(size_t)r * 512 + c0] = o0;
                float4 o1 = *(const float4*)&M[(size_t)r * 512 + c0 + 256];
                o1.x -= v2.x; o1.y -= v2.y; o1.z -= v3.x; o1.w -= v3.y;
                if (pivB) {
                    int cb = c0 + 256 - k0;
                    o1.x -= sCtc[(cb + 0) * 68 + rr];
                    o1.y -= sCtc[(cb + 1) * 68 + rr];
                    o1.z -= sCtc[(cb + 2) * 68 + rr];
                    o1.w -= sCtc[(cb + 3) * 68 + rr];
                }
                *(float4*)&M[(size_t)r * 512 + c0 + 256] = o1;
            }

            if (nxt >= 0) {
#pragma unroll
                for (int t = 0; t < 8; t++) {
                    int idx = tid + t * 512;
                    int rr = idx >> 6, k = idx & 63;
                    sCtn[k * 68 + rr] = pf[t];
                }
            }
            __syncthreads();
            buf ^= 1;
        }
    }
    g_diag[blockIdx.x * 512 + ((tid + 1) & 511)] = M[(size_t)tid * 512 + tid];
}

// ===== K8: att[i][j] = A[j][i] * ((i!=0)*diag[i] - (j!=0)*LLinv[i][j]) =====
__global__ __launch_bounds__(1024) void out_kernel(float* __restrict__ out)
{
    __shared__ float sA[32][33];
    const int bt = blockIdx.z;
    const int i0 = blockIdx.y * 32, j0 = blockIdx.x * 32;
    const int txx = threadIdx.x, tyy = threadIdx.y;
    const float* Abt = g_A + (size_t)bt * LL_;
    sA[tyy][txx] = Abt[(size_t)(j0 + tyy) * 512 + i0 + txx];
    __syncthreads();
    const int i = i0 + tyy, j = j0 + txx;
    const float Aji = sA[txx][tyy];
    const float ll = g_W[(size_t)bt * LL_ + (size_t)((i - 1) & 511) * 512 + ((j - 1) & 511)];
    const float dg = g_diag[bt * 512 + i];
    const float v = Aji * ((i ? dg : 0.f) - (j ? ll : 0.f));
    out[((size_t)bt * 512 + i) * 512 + j] = v;
}

extern "C" void kernel_launch(void* const* d_in, const int* in_sizes, int n_in,
                              void* d_out, int out_size)
{
    const float* X     = (const float*)d_in[0];
    const int*   mask  = (const int*)d_in[1];
    const float* Wq    = (const float*)d_in[2];
    const float* bq    = (const float*)d_in[3];
    const float* Wk    = (const float*)d_in[4];
    const float* bk    = (const float*)d_in[5];
    const float* Wroot = (const float*)d_in[6];
    const float* broot = (const float*)d_in[7];
    float* out = (float*)d_out;

    proj_kernel<<<dim3(6, 128, 2), 256>>>(X, Wq, bq, Wk, bk);
    scores_kernel<<<dim3(4, 4, 256), 256>>>(mask);
    softmax_kernel<<<BT_ * 512, 256>>>();
    f_kernel<<<2048, 256>>>(X, Wroot, broot);
    deg_kernel<<<BT_, 512>>>();
    build_kernel<<<dim3(512, BT_), 512>>>();
    cudaFuncSetAttribute(invert_kernel, cudaFuncAttributeMaxDynamicSharedMemorySize,
                         SMEM_INV_BYTES);
    invert_kernel<<<BT_, 512, SMEM_INV_BYTES>>>();
    out_kernel<<<dim3(16, 16, BT_), dim3(32, 32)>>>(out);
}

// round 15
// speedup vs baseline: 1.0003x; 1.0003x over previous
#include <cuda_runtime.h>
#include <math.h>

#define B_   32
#define L_   512
#define H_   768
#define T_   8
#define DK_  96
#define BT_  256
#define LL_  (512*512)

// ---------------- f32x2 packed helpers ----------------
__device__ __forceinline__ unsigned long long pk2(float x, float y) {
    unsigned long long r;
    asm("mov.b64 %0, {%1, %2};" : "=l"(r) : "f"(x), "f"(y));
    return r;
}
__device__ __forceinline__ float2 unpk(unsigned long long v) {
    float2 f;
    asm("mov.b64 {%0, %1}, %2;" : "=f"(f.x), "=f"(f.y) : "l"(v));
    return f;
}
#define FMA2(d, a, b) asm("fma.rn.f32x2 %0, %1, %2, %0;" : "+l"(d) : "l"(a), "l"(b))

// ---------------- tf32 helpers ----------------
__device__ __forceinline__ unsigned cvt_tf32(float x) {
    unsigned u;
    asm("cvt.rna.tf32.f32 %0, %1;" : "=r"(u) : "f"(x));
    return u;
}
#define MMA_TF32(c, a, b) \
    asm("mma.sync.aligned.m16n8k8.row.col.f32.tf32.tf32.f32 " \
        "{%0,%1,%2,%3},{%4,%5,%6,%7},{%8,%9},{%0,%1,%2,%3};" \
        : "+f"((c)[0]), "+f"((c)[1]), "+f"((c)[2]), "+f"((c)[3]) \
        : "r"((a)[0]), "r"((a)[1]), "r"((a)[2]), "r"((a)[3]), \
          "r"((b)[0]), "r"((b)[1]))

// ---------------- scratch ----------------
__device__ float g_Q[16384 * 768];
__device__ float g_K[16384 * 768];
__device__ float g_A[(size_t)BT_ * LL_];
__device__ float g_W[(size_t)BT_ * LL_];
__device__ float g_f[BT_ * 512];
__device__ float g_deg[BT_ * 512];
__device__ float g_diag[BT_ * 512];

// ================= K1: Q = X@Wq^T+bq ; K = X@Wk^T+bk (tf32 MMA) =================
__global__ __launch_bounds__(256) void proj_kernel(
    const float* __restrict__ X,
    const float* __restrict__ Wq, const float* __restrict__ bq,
    const float* __restrict__ Wk, const float* __restrict__ bk)
{
    __shared__ unsigned As[128 * 36];
    __shared__ unsigned Bs[128 * 36];
    const int z = blockIdx.z;
    const float* Wm   = z ? Wk : Wq;
    const float* bias = z ? bk : bq;
    float*       Out  = z ? g_K : g_Q;
    const int bm = blockIdx.y, bn = blockIdx.x;
    const int tid = threadIdx.x;
    const int warp = tid >> 5, lane = tid & 31;
    const int wm = warp >> 2, wn = warp & 3;
    const int grp = lane >> 2, tig = lane & 3;

    float acc[4][4][4];
#pragma unroll
    for (int i = 0; i < 4; i++)
#pragma unroll
        for (int j = 0; j < 4; j++)
#pragma unroll
            for (int k = 0; k < 4; k++) acc[i][j][k] = 0.f;

    const int r  = tid >> 1;
    const int kp = (tid & 1) * 16;
    const float* Ag = X  + (size_t)(bm * 128 + r) * H_ + kp;
    const float* Bg = Wm + (size_t)(bn * 128 + r) * H_ + kp;
    unsigned* Asw = As + r * 36 + kp;
    unsigned* Bsw = Bs + r * 36 + kp;

    for (int c0 = 0; c0 < H_; c0 += 32) {
#pragma unroll
        for (int v = 0; v < 4; v++) {
            float4 a4 = *(const float4*)(Ag + c0 + v * 4);
            float4 b4 = *(const float4*)(Bg + c0 + v * 4);
            uint4 ua = make_uint4(cvt_tf32(a4.x), cvt_tf32(a4.y), cvt_tf32(a4.z), cvt_tf32(a4.w));
            uint4 ub = make_uint4(cvt_tf32(b4.x), cvt_tf32(b4.y), cvt_tf32(b4.z), cvt_tf32(b4.w));
            *(uint4*)(Asw + v * 4) = ua;
            *(uint4*)(Bsw + v * 4) = ub;
        }
        __syncthreads();
#pragma unroll
        for (int ks = 0; ks < 4; ks++) {
            const int kb = ks * 8;
            unsigned a[4][4], b[4][2];
#pragma unroll
            for (int mi = 0; mi < 4; mi++) {
                const int base = (wm * 64 + mi * 16) * 36 + kb;
                a[mi][0] = As[base + grp * 36 + tig];
                a[mi][1] = As[base + (grp + 8) * 36 + tig];
                a[mi][2] = As[base + grp * 36 + tig + 4];
                a[mi][3] = As[base + (grp + 8) * 36 + tig + 4];
            }
#pragma unroll
            for (int ni = 0; ni < 4; ni++) {
                const int nbase = (wn * 32 + ni * 8 + grp) * 36 + kb;
                b[ni][0] = Bs[nbase + tig];
                b[ni][1] = Bs[nbase + tig + 4];
            }
#pragma unroll
            for (int mi = 0; mi < 4; mi++)
#pragma unroll
                for (int ni = 0; ni < 4; ni++)
                    MMA_TF32(acc[mi][ni], a[mi], b[ni]);
        }
        __syncthreads();
    }
#pragma unroll
    for (int mi = 0; mi < 4; mi++) {
        const int row = bm * 128 + wm * 64 + mi * 16 + grp;
#pragma unroll
        for (int ni = 0; ni < 4; ni++) {
            const int col = bn * 128 + wn * 32 + ni * 8 + 2 * tig;
            float2 bb = *(const float2*)(bias + col);
            float2 o0 = make_float2(acc[mi][ni][0] + bb.x, acc[mi][ni][1] + bb.y);
            float2 o1 = make_float2(acc[mi][ni][2] + bb.x, acc[mi][ni][3] + bb.y);
            *(float2*)(Out + (size_t)row * H_ + col)       = o0;
            *(float2*)(Out + (size_t)(row + 8) * H_ + col) = o1;
        }
    }
}

// ================= K2: scores -> g_A (tf32 MMA, scaled + masked) =================
__global__ __launch_bounds__(256) void scores_kernel(const int* __restrict__ mask)
{
    __shared__ unsigned As[128 * 36];
    __shared__ unsigned Bs[128 * 36];
    const int bt = blockIdx.z;
    const int b = bt >> 3, t = bt & 7;
    const int bm = blockIdx.y, bn = blockIdx.x;
    const int tid = threadIdx.x;
    const int warp = tid >> 5, lane = tid & 31;
    const int wm = warp >> 2, wn = warp & 3;
    const int grp = lane >> 2, tig = lane & 3;

    float acc[4][4][4];
#pragma unroll
    for (int i = 0; i < 4; i++)
#pragma unroll
        for (int j = 0; j < 4; j++)
#pragma unroll
            for (int k = 0; k < 4; k++) acc[i][j][k] = 0.f;

    const int r  = tid >> 1;
    const int kp = (tid & 1) * 16;
    const float* Ag = g_Q + (size_t)(b * 512 + bm * 128 + r) * H_ + t * DK_ + kp;
    const float* Bg = g_K + (size_t)(b * 512 + bn * 128 + r) * H_ + t * DK_ + kp;
    unsigned* Asw = As + r * 36 + kp;
    unsigned* Bsw = Bs + r * 36 + kp;

    for (int c0 = 0; c0 < DK_; c0 += 32) {
#pragma unroll
        for (int v = 0; v < 4; v++) {
            float4 a4 = *(const float4*)(Ag + c0 + v * 4);
            float4 b4 = *(const float4*)(Bg + c0 + v * 4);
            uint4 ua = make_uint4(cvt_tf32(a4.x), cvt_tf32(a4.y), cvt_tf32(a4.z), cvt_tf32(a4.w));
            uint4 ub = make_uint4(cvt_tf32(b4.x), cvt_tf32(b4.y), cvt_tf32(b4.z), cvt_tf32(b4.w));
            *(uint4*)(Asw + v * 4) = ua;
            *(uint4*)(Bsw + v * 4) = ub;
        }
        __syncthreads();
#pragma unroll
        for (int ks = 0; ks < 4; ks++) {
            const int kb = ks * 8;
            unsigned a[4][4], bfr[4][2];
#pragma unroll
            for (int mi = 0; mi < 4; mi++) {
                const int base = (wm * 64 + mi * 16) * 36 + kb;
                a[mi][0] = As[base + grp * 36 + tig];
                a[mi][1] = As[base + (grp + 8) * 36 + tig];
                a[mi][2] = As[base + grp * 36 + tig + 4];
                a[mi][3] = As[base + (grp + 8) * 36 + tig + 4];
            }
#pragma unroll
            for (int ni = 0; ni < 4; ni++) {
                const int nbase = (wn * 32 + ni * 8 + grp) * 36 + kb;
                bfr[ni][0] = Bs[nbase + tig];
                bfr[ni][1] = Bs[nbase + tig + 4];
            }
#pragma unroll
            for (int mi = 0; mi < 4; mi++)
#pragma unroll
                for (int ni = 0; ni < 4; ni++)
                    MMA_TF32(acc[mi][ni], a[mi], bfr[ni]);
        }
        __syncthreads();
    }
    const float scale = 0.10206207261596575f;
    float* Om = g_A + (size_t)bt * LL_;
#pragma unroll
    for (int mi = 0; mi < 4; mi++) {
        const int row = bm * 128 + wm * 64 + mi * 16 + grp;
#pragma unroll
        for (int ni = 0; ni < 4; ni++) {
            const int col = bn * 128 + wn * 32 + ni * 8 + 2 * tig;
            int2 mv = *(const int2*)(mask + b * 512 + col);
            float2 o0 = make_float2(
                mv.x ? acc[mi][ni][0] * scale : -1000000000.0f,
                mv.y ? acc[mi][ni][1] * scale : -1000000000.0f);
            float2 o1 = make_float2(
                mv.x ? acc[mi][ni][2] * scale : -1000000000.0f,
                mv.y ? acc[mi][ni][3] * scale : -1000000000.0f);
            *(float2*)(Om + (size_t)row * 512 + col)       = o0;
            *(float2*)(Om + (size_t)(row + 8) * 512 + col) = o1;
        }
    }
}

// ========== K3: per row: A = exp(softmax(s)), zero diagonal (in place) ==========
__global__ __launch_bounds__(256) void softmax_kernel()
{
    const int row = blockIdx.x;
    const int q = row & 511;
    float* r = g_A + (size_t)row * 512;
    const int tid = threadIdx.x;
    float v0 = r[tid], v1 = r[tid + 256];

    __shared__ float red[16];
    float m = fmaxf(v0, v1);
#pragma unroll
    for (int o = 16; o; o >>= 1) m = fmaxf(m, __shfl_xor_sync(0xffffffffu, m, o));
    if ((tid & 31) == 0) red[tid >> 5] = m;
    __syncthreads();
    m = fmaxf(fmaxf(fmaxf(red[0], red[1]), fmaxf(red[2], red[3])),
              fmaxf(fmaxf(red[4], red[5]), fmaxf(red[6], red[7])));

    float e0 = expf(v0 - m), e1 = expf(v1 - m);
    float s = e0 + e1;
#pragma unroll
    for (int o = 16; o; o >>= 1) s += __shfl_xor_sync(0xffffffffu, s, o);
    if ((tid & 31) == 0) red[8 + (tid >> 5)] = s;
    __syncthreads();
    s = ((red[8] + red[9]) + (red[10] + red[11])) +
        ((red[12] + red[13]) + (red[14] + red[15]));
    const float inv = 1.0f / s;

    float a0 = expf(e0 * inv); if (tid == q)       a0 = 0.f;
    float a1 = expf(e1 * inv); if (tid + 256 == q) a1 = 0.f;
    r[tid] = a0; r[tid + 256] = a1;
}

// ================= K4: f[bt][l] = x[b,l,:].Wroot[t,:] + broot[t] =================
__global__ __launch_bounds__(256) void f_kernel(const float* __restrict__ x,
                                                const float* __restrict__ Wroot,
                                                const float* __restrict__ broot)
{
    __shared__ float sW[T_ * H_];
    for (int idx = threadIdx.x; idx < T_ * H_; idx += 256) sW[idx] = Wroot[idx];
    __syncthreads();
    const int w = threadIdx.x >> 5, lane = threadIdx.x & 31;
    const int bl = blockIdx.x * 8 + w;
    const int b = bl >> 9, l = bl & 511;
    const float* xr = x + (size_t)bl * H_;
    float xv[24];
#pragma unroll
    for (int i = 0; i < 24; i++) xv[i] = xr[lane + i * 32];
#pragma unroll
    for (int t = 0; t < T_; t++) {
        float s = 0.f;
#pragma unroll
        for (int i = 0; i < 24; i++) s += xv[i] * sW[t * H_ + lane + i * 32];
#pragma unroll
        for (int o = 16; o; o >>= 1) s += __shfl_xor_sync(0xffffffffu, s, o);
        if (lane == 0) g_f[(b * T_ + t) * 512 + l] = s + broot[t];
    }
}

// ================= K5: deg[bt][k] = sum_q A[bt][q][k] =================
__global__ __launch_bounds__(512) void deg_kernel()
{
    const int bt = blockIdx.x, k = threadIdx.x;
    const float* Am = g_A + (size_t)bt * LL_ + k;
    float s0 = 0, s1 = 0, s2 = 0, s3 = 0;
    for (int q = 0; q < 512; q += 4) {
        s0 += Am[(size_t)q * 512];
        s1 += Am[(size_t)(q + 1) * 512];
        s2 += Am[(size_t)(q + 2) * 512];
        s3 += Am[(size_t)(q + 3) * 512];
    }
    g_deg[bt * 512 + k] = (s0 + s1) + (s2 + s3);
}

// ===== K6: permuted Lbar: W[i][j] = Lbar[(i+1)&511][(j+1)&511] =====
__global__ __launch_bounds__(512) void build_kernel()
{
    const int i = blockIdx.x, bt = blockIdx.y, j = threadIdx.x;
    const int pi = (i + 1) & 511, pj = (j + 1) & 511;
    float v;
    if (pi == 0) {
        v = g_f[bt * 512 + pj];
    } else {
        v = -g_A[(size_t)bt * LL_ + (size_t)pi * 512 + pj];
        if (pi == pj) v += g_deg[bt * 512 + pj];
    }
    g_W[(size_t)bt * LL_ + (size_t)i * 512 + j] = v;
}

// ===== K7: blocked Gauss-Jordan inverse (nb=64, no pivoting, all-fp32 FFMA2) =====
// Phase C double-buffered Ct + L2 prefetch of epilogue RMW lines.
// smem floats: sRP[64*512]=32768, sG[64*72]=4608, sCt0/sCt1[64*68]=4352 each,
//              sck[64], srk[64]
#define IV_RP  0
#define IV_G   32768
#define IV_CT0 (32768 + 4608)
#define IV_CT1 (32768 + 4608 + 4352)
#define IV_CK  (32768 + 4608 + 4352 + 4352)
#define IV_RK  (32768 + 4608 + 4352 + 4352 + 64)
#define SMEM_INV_FLOATS (32768 + 4608 + 4352 + 4352 + 128)
#define SMEM_INV_BYTES (SMEM_INV_FLOATS * 4)

__global__ __launch_bounds__(512) void invert_kernel()
{
    extern __shared__ float sm[];
    float* sRP  = sm + IV_RP;
    float* sG   = sm + IV_G;
    float* sCt0 = sm + IV_CT0;
    float* sCt1 = sm + IV_CT1;
    float* sck  = sm + IV_CK;
    float* srk  = sm + IV_RK;
    float* M = g_W + (size_t)blockIdx.x * LL_;
    const int tid = threadIdx.x;
    const int tx = tid & 63, ty = tid >> 6;
    const int c0 = tx * 4;
    const int ty8 = ty * 8;

    for (int s = 0; s < 8; s++) {
        const int k0 = s * 64;

        // ---- Phase A: load G = D^T, invert via GJ (G becomes (D^-1)^T) ----
        for (int idx = tid; idx < 4096; idx += 512) {
            int bb = idx >> 6, aa = idx & 63;
            sG[aa * 72 + bb] = M[(size_t)(k0 + bb) * 512 + k0 + aa];
        }
        __syncthreads();
        for (int k = 0; k < 64; k++) {
            if (tid < 64) { sck[tid] = sG[tid * 72 + k]; srk[tid] = sG[k * 72 + tid]; }
            __syncthreads();
            const float p = 1.0f / srk[k];
            for (int idx = tid; idx < 4096; idx += 512) {
                int i2 = idx >> 6, j2 = idx & 63;
                float v;
                if (i2 == k)      v = (j2 == k) ? p : srk[j2] * p;
                else if (j2 == k) v = -sck[i2] * p;
                else              v = sG[i2 * 72 + j2] - sck[i2] * (srk[j2] * p);
                sG[i2 * 72 + j2] = v;
            }
            __syncthreads();
        }

        // ---- Phase B: pivot rows S = Dinv*OldRows (FFMA2); write M + sRP ----
        {
            const int c = tid;
            const bool piv = (c >= k0) && (c < k0 + 64);
            const int cc = c - k0;
            unsigned long long acc2[32];
#pragma unroll
            for (int m = 0; m < 32; m++) acc2[m] = 0ull;
#pragma unroll 4
            for (int k = 0; k < 64; k++) {
                float rk = M[(size_t)(k0 + k) * 512 + c];
                unsigned long long ak = pk2(rk, rk);
                const ulonglong2* gp = (const ulonglong2*)&sG[k * 72];
#pragma unroll
                for (int m = 0; m < 16; m++) {
                    ulonglong2 g2 = gp[m];
                    FMA2(acc2[2 * m],     ak, g2.x);
                    FMA2(acc2[2 * m + 1], ak, g2.y);
                }
            }
#pragma unroll
            for (int m = 0; m < 32; m++) {
                float2 v = unpk(acc2[m]);
                int r0 = 2 * m, r1 = 2 * m + 1;
                float a0 = piv ? sG[cc * 72 + r0] : v.x;
                float a1 = piv ? sG[cc * 72 + r1] : v.y;
                sRP[r0 * 512 + c] = a0;
                sRP[r1 * 512 + c] = a1;
                M[(size_t)(k0 + r0) * 512 + c] = a0;
                M[(size_t)(k0 + r1) * 512 + c] = a1;
            }
        }
        __syncthreads();

        // ---- preload first rb's Ct into buffer 0 ----
        {
            const int rb0 = (s == 0) ? 1 : 0;
            const int nrow0 = rb0 * 64;
#pragma unroll
            for (int t = 0; t < 8; t++) {
                int idx = tid + t * 512;
                int rr = idx >> 6, k = idx & 63;
                sCt0[k * 68 + rr] = M[(size_t)(nrow0 + rr) * 512 + k0 + k];
            }
        }
        __syncthreads();

        // ---- Phase C: trailing update (FFMA2 8x8), double-buffered Ct ----
        int buf = 0;
        for (int ii = 0; ii < 7; ii++) {
            const int rb  = ii + (ii >= s ? 1 : 0);
            const int nn  = ii + 1;
            const int nxt = (nn < 7) ? (nn + (nn >= s ? 1 : 0)) : -1;
            const int row0 = rb * 64;
            float* sCtc = buf ? sCt1 : sCt0;
            float* sCtn = buf ? sCt0 : sCt1;

            // prefetch next rb's Ct into registers (hidden under compute)
            float pf[8];
            if (nxt >= 0) {
                const int nrow0 = nxt * 64;
#pragma unroll
                for (int t = 0; t < 8; t++) {
                    int idx = tid + t * 512;
                    int rr = idx >> 6, k = idx & 63;
                    pf[t] = M[(size_t)(nrow0 + rr) * 512 + k0 + k];
                }
            }
            // L2 prefetch of the epilogue RMW lines (one thread per 128B line)
            if ((tx & 7) == 0) {
#pragma unroll
                for (int i = 0; i < 8; i++) {
                    const float* p0 = &M[(size_t)(row0 + ty8 + i) * 512 + c0];
                    asm volatile("prefetch.global.L2 [%0];" :: "l"(p0));
                    asm volatile("prefetch.global.L2 [%0];" :: "l"(p0 + 256));
                }
            }

            unsigned long long acc2[8][4];
#pragma unroll
            for (int i = 0; i < 8; i++)
#pragma unroll
                for (int j = 0; j < 4; j++) acc2[i][j] = 0ull;

#pragma unroll 4
            for (int k = 0; k < 64; k++) {
                float a[8];
                *(float4*)(a)     = *(const float4*)&sCtc[k * 68 + ty8];
                *(float4*)(a + 4) = *(const float4*)&sCtc[k * 68 + ty8 + 4];
                ulonglong2 b0 = *(const ulonglong2*)&sRP[k * 512 + c0];
                ulonglong2 b1 = *(const ulonglong2*)&sRP[k * 512 + c0 + 256];
#pragma unroll
                for (int i = 0; i < 8; i++) {
                    unsigned long long aa = pk2(a[i], a[i]);
                    FMA2(acc2[i][0], aa, b0.x);
                    FMA2(acc2[i][1], aa, b0.y);
                    FMA2(acc2[i][2], aa, b1.x);
                    FMA2(acc2[i][3], aa, b1.y);
                }
            }

            const bool pivA = (c0 >= k0) && (c0 < k0 + 64);
            const bool pivB = (c0 + 256 >= k0) && (c0 + 256 < k0 + 64);
#pragma unroll
            for (int i = 0; i < 8; i++) {
                const int rr = ty8 + i;
                const int r = row0 + rr;
                float2 v0 = unpk(acc2[i][0]), v1 = unpk(acc2[i][1]);
                float2 v2 = unpk(acc2[i][2]), v3 = unpk(acc2[i][3]);
                float4 o0 = *(const float4*)&M[(size_t)r * 512 + c0];
                o0.x -= v0.x; o0.y -= v0.y; o0.z -= v1.x; o0.w -= v1.y;
                if (pivA) {
                    int cb = c0 - k0;
                    o0.x -= sCtc[(cb + 0) * 68 + rr];
                    o0.y -= sCtc[(cb + 1) * 68 + rr];
                    o0.z -= sCtc[(cb + 2) * 68 + rr];
                    o0.w -= sCtc[(cb + 3) * 68 + rr];
                }
                *(float4*)&M[(size_t)r * 512 + c0] = o0;
                float4 o1 = *(const float4*)&M[(size_t)r * 512 + c0 + 256];
                o1.x -= v2.x; o1.y -= v2.y; o1.z -= v3.x; o1.w -= v3.y;
                if (pivB) {
                    int cb = c0 + 256 - k0;
                    o1.x -= sCtc[(cb + 0) * 68 + rr];
                    o1.y -= sCtc[(cb + 1) * 68 + rr];
                    o1.z -= sCtc[(cb + 2) * 68 + rr];
                    o1.w -= sCtc[(cb + 3) * 68 + rr];
                }
                *(float4*)&M[(size_t)r * 512 + c0 + 256] = o1;
            }

            if (nxt >= 0) {
#pragma unroll
                for (int t = 0; t < 8; t++) {
                    int idx = tid + t * 512;
                    int rr = idx >> 6, k = idx & 63;
                    sCtn[k * 68 + rr] = pf[t];
                }
            }
            __syncthreads();
            buf ^= 1;
        }
    }
    g_diag[blockIdx.x * 512 + ((tid + 1) & 511)] = M[(size_t)tid * 512 + tid];
}

// ===== K8: att[i][j] = A[j][i] * ((i!=0)*diag[i] - (j!=0)*LLinv[i][j]) =====
__global__ __launch_bounds__(1024) void out_kernel(float* __restrict__ out)
{
    __shared__ float sA[32][33];
    const int bt = blockIdx.z;
    const int i0 = blockIdx.y * 32, j0 = blockIdx.x * 32;
    const int txx = threadIdx.x, tyy = threadIdx.y;
    const float* Abt = g_A + (size_t)bt * LL_;
    sA[tyy][txx] = Abt[(size_t)(j0 + tyy) * 512 + i0 + txx];
    __syncthreads();
    const int i = i0 + tyy, j = j0 + txx;
    const float Aji = sA[txx][tyy];
    const float ll = g_W[(size_t)bt * LL_ + (size_t)((i - 1) & 511) * 512 + ((j - 1) & 511)];
    const float dg = g_diag[bt * 512 + i];
    const float v = Aji * ((i ? dg : 0.f) - (j ? ll : 0.f));
    out[((size_t)bt * 512 + i) * 512 + j] = v;
}

extern "C" void kernel_launch(void* const* d_in, const int* in_sizes, int n_in,
                              void* d_out, int out_size)
{
    const float* X     = (const float*)d_in[0];
    const int*   mask  = (const int*)d_in[1];
    const float* Wq    = (const float*)d_in[2];
    const float* bq    = (const float*)d_in[3];
    const float* Wk    = (const float*)d_in[4];
    const float* bk    = (const float*)d_in[5];
    const float* Wroot = (const float*)d_in[6];
    const float* broot = (const float*)d_in[7];
    float* out = (float*)d_out;

    proj_kernel<<<dim3(6, 128, 2), 256>>>(X, Wq, bq, Wk, bk);
    scores_kernel<<<dim3(4, 4, 256), 256>>>(mask);
    softmax_kernel<<<BT_ * 512, 256>>>();
    f_kernel<<<2048, 256>>>(X, Wroot, broot);
    deg_kernel<<<BT_, 512>>>();
    build_kernel<<<dim3(512, BT_), 512>>>();
    cudaFuncSetAttribute(invert_kernel, cudaFuncAttributeMaxDynamicSharedMemorySize,
                         SMEM_INV_BYTES);
    invert_kernel<<<BT_, 512, SMEM_INV_BYTES>>>();
    out_kernel<<<dim3(16, 16, BT_), dim3(32, 32)>>>(out);
}

// round 16
// speedup vs baseline: 1.0015x; 1.0012x over previous
#include <cuda_runtime.h>
#include <math.h>

#define B_   32
#define L_   512
#define H_   768
#define T_   8
#define DK_  96
#define BT_  256
#define LL_  (512*512)

// ---------------- f32x2 packed helpers ----------------
__device__ __forceinline__ unsigned long long pk2(float x, float y) {
    unsigned long long r;
    asm("mov.b64 %0, {%1, %2};" : "=l"(r) : "f"(x), "f"(y));
    return r;
}
__device__ __forceinline__ float2 unpk(unsigned long long v) {
    float2 f;
    asm("mov.b64 {%0, %1}, %2;" : "=f"(f.x), "=f"(f.y) : "l"(v));
    return f;
}
#define FMA2(d, a, b) asm("fma.rn.f32x2 %0, %1, %2, %0;" : "+l"(d) : "l"(a), "l"(b))

// ---------------- tf32 helpers ----------------
__device__ __forceinline__ unsigned cvt_tf32(float x) {
    unsigned u;
    asm("cvt.rna.tf32.f32 %0, %1;" : "=r"(u) : "f"(x));
    return u;
}
#define MMA_TF32(c, a, b) \
    asm("mma.sync.aligned.m16n8k8.row.col.f32.tf32.tf32.f32 " \
        "{%0,%1,%2,%3},{%4,%5,%6,%7},{%8,%9},{%0,%1,%2,%3};" \
        : "+f"((c)[0]), "+f"((c)[1]), "+f"((c)[2]), "+f"((c)[3]) \
        : "r"((a)[0]), "r"((a)[1]), "r"((a)[2]), "r"((a)[3]), \
          "r"((b)[0]), "r"((b)[1]))

// ---------------- scratch ----------------
__device__ float g_Q[16384 * 768];
__device__ float g_K[16384 * 768];
__device__ float g_A[(size_t)BT_ * LL_];
__device__ float g_W[(size_t)BT_ * LL_];
__device__ float g_f[BT_ * 512];
__device__ float g_deg[BT_ * 512];
__device__ float g_diag[BT_ * 512];

// ================= K1: Q = X@Wq^T+bq ; K = X@Wk^T+bk (tf32 MMA) =================
__global__ __launch_bounds__(256) void proj_kernel(
    const float* __restrict__ X,
    const float* __restrict__ Wq, const float* __restrict__ bq,
    const float* __restrict__ Wk, const float* __restrict__ bk)
{
    __shared__ unsigned As[128 * 36];
    __shared__ unsigned Bs[128 * 36];
    const int z = blockIdx.z;
    const float* Wm   = z ? Wk : Wq;
    const float* bias = z ? bk : bq;
    float*       Out  = z ? g_K : g_Q;
    const int bm = blockIdx.y, bn = blockIdx.x;
    const int tid = threadIdx.x;
    const int warp = tid >> 5, lane = tid & 31;
    const int wm = warp >> 2, wn = warp & 3;
    const int grp = lane >> 2, tig = lane & 3;

    float acc[4][4][4];
#pragma unroll
    for (int i = 0; i < 4; i++)
#pragma unroll
        for (int j = 0; j < 4; j++)
#pragma unroll
            for (int k = 0; k < 4; k++) acc[i][j][k] = 0.f;

    const int r  = tid >> 1;
    const int kp = (tid & 1) * 16;
    const float* Ag = X  + (size_t)(bm * 128 + r) * H_ + kp;
    const float* Bg = Wm + (size_t)(bn * 128 + r) * H_ + kp;
    unsigned* Asw = As + r * 36 + kp;
    unsigned* Bsw = Bs + r * 36 + kp;

    for (int c0 = 0; c0 < H_; c0 += 32) {
#pragma unroll
        for (int v = 0; v < 4; v++) {
            float4 a4 = *(const float4*)(Ag + c0 + v * 4);
            float4 b4 = *(const float4*)(Bg + c0 + v * 4);
            uint4 ua = make_uint4(cvt_tf32(a4.x), cvt_tf32(a4.y), cvt_tf32(a4.z), cvt_tf32(a4.w));
            uint4 ub = make_uint4(cvt_tf32(b4.x), cvt_tf32(b4.y), cvt_tf32(b4.z), cvt_tf32(b4.w));
            *(uint4*)(Asw + v * 4) = ua;
            *(uint4*)(Bsw + v * 4) = ub;
        }
        __syncthreads();
#pragma unroll
        for (int ks = 0; ks < 4; ks++) {
            const int kb = ks * 8;
            unsigned a[4][4], b[4][2];
#pragma unroll
            for (int mi = 0; mi < 4; mi++) {
                const int base = (wm * 64 + mi * 16) * 36 + kb;
                a[mi][0] = As[base + grp * 36 + tig];
                a[mi][1] = As[base + (grp + 8) * 36 + tig];
                a[mi][2] = As[base + grp * 36 + tig + 4];
                a[mi][3] = As[base + (grp + 8) * 36 + tig + 4];
            }
#pragma unroll
            for (int ni = 0; ni < 4; ni++) {
                const int nbase = (wn * 32 + ni * 8 + grp) * 36 + kb;
                b[ni][0] = Bs[nbase + tig];
                b[ni][1] = Bs[nbase + tig + 4];
            }
#pragma unroll
            for (int mi = 0; mi < 4; mi++)
#pragma unroll
                for (int ni = 0; ni < 4; ni++)
                    MMA_TF32(acc[mi][ni], a[mi], b[ni]);
        }
        __syncthreads();
    }
#pragma unroll
    for (int mi = 0; mi < 4; mi++) {
        const int row = bm * 128 + wm * 64 + mi * 16 + grp;
#pragma unroll
        for (int ni = 0; ni < 4; ni++) {
            const int col = bn * 128 + wn * 32 + ni * 8 + 2 * tig;
            float2 bb = *(const float2*)(bias + col);
            float2 o0 = make_float2(acc[mi][ni][0] + bb.x, acc[mi][ni][1] + bb.y);
            float2 o1 = make_float2(acc[mi][ni][2] + bb.x, acc[mi][ni][3] + bb.y);
            *(float2*)(Out + (size_t)row * H_ + col)       = o0;
            *(float2*)(Out + (size_t)(row + 8) * H_ + col) = o1;
        }
    }
}

// ================= K2: scores -> g_A (tf32 MMA, scaled + masked) =================
__global__ __launch_bounds__(256) void scores_kernel(const int* __restrict__ mask)
{
    __shared__ unsigned As[128 * 36];
    __shared__ unsigned Bs[128 * 36];
    const int bt = blockIdx.z;
    const int b = bt >> 3, t = bt & 7;
    const int bm = blockIdx.y, bn = blockIdx.x;
    const int tid = threadIdx.x;
    const int warp = tid >> 5, lane = tid & 31;
    const int wm = warp >> 2, wn = warp & 3;
    const int grp = lane >> 2, tig = lane & 3;

    float acc[4][4][4];
#pragma unroll
    for (int i = 0; i < 4; i++)
#pragma unroll
        for (int j = 0; j < 4; j++)
#pragma unroll
            for (int k = 0; k < 4; k++) acc[i][j][k] = 0.f;

    const int r  = tid >> 1;
    const int kp = (tid & 1) * 16;
    const float* Ag = g_Q + (size_t)(b * 512 + bm * 128 + r) * H_ + t * DK_ + kp;
    const float* Bg = g_K + (size_t)(b * 512 + bn * 128 + r) * H_ + t * DK_ + kp;
    unsigned* Asw = As + r * 36 + kp;
    unsigned* Bsw = Bs + r * 36 + kp;

    for (int c0 = 0; c0 < DK_; c0 += 32) {
#pragma unroll
        for (int v = 0; v < 4; v++) {
            float4 a4 = *(const float4*)(Ag + c0 + v * 4);
            float4 b4 = *(const float4*)(Bg + c0 + v * 4);
            uint4 ua = make_uint4(cvt_tf32(a4.x), cvt_tf32(a4.y), cvt_tf32(a4.z), cvt_tf32(a4.w));
            uint4 ub = make_uint4(cvt_tf32(b4.x), cvt_tf32(b4.y), cvt_tf32(b4.z), cvt_tf32(b4.w));
            *(uint4*)(Asw + v * 4) = ua;
            *(uint4*)(Bsw + v * 4) = ub;
        }
        __syncthreads();
#pragma unroll
        for (int ks = 0; ks < 4; ks++) {
            const int kb = ks * 8;
            unsigned a[4][4], bfr[4][2];
#pragma unroll
            for (int mi = 0; mi < 4; mi++) {
                const int base = (wm * 64 + mi * 16) * 36 + kb;
                a[mi][0] = As[base + grp * 36 + tig];
                a[mi][1] = As[base + (grp + 8) * 36 + tig];
                a[mi][2] = As[base + grp * 36 + tig + 4];
                a[mi][3] = As[base + (grp + 8) * 36 + tig + 4];
            }
#pragma unroll
            for (int ni = 0; ni < 4; ni++) {
                const int nbase = (wn * 32 + ni * 8 + grp) * 36 + kb;
                bfr[ni][0] = Bs[nbase + tig];
                bfr[ni][1] = Bs[nbase + tig + 4];
            }
#pragma unroll
            for (int mi = 0; mi < 4; mi++)
#pragma unroll
                for (int ni = 0; ni < 4; ni++)
                    MMA_TF32(acc[mi][ni], a[mi], bfr[ni]);
        }
        __syncthreads();
    }
    const float scale = 0.10206207261596575f;
    float* Om = g_A + (size_t)bt * LL_;
#pragma unroll
    for (int mi = 0; mi < 4; mi++) {
        const int row = bm * 128 + wm * 64 + mi * 16 + grp;
#pragma unroll
        for (int ni = 0; ni < 4; ni++) {
            const int col = bn * 128 + wn * 32 + ni * 8 + 2 * tig;
            int2 mv = *(const int2*)(mask + b * 512 + col);
            float2 o0 = make_float2(
                mv.x ? acc[mi][ni][0] * scale : -1000000000.0f,
                mv.y ? acc[mi][ni][1] * scale : -1000000000.0f);
            float2 o1 = make_float2(
                mv.x ? acc[mi][ni][2] * scale : -1000000000.0f,
                mv.y ? acc[mi][ni][3] * scale : -1000000000.0f);
            *(float2*)(Om + (size_t)row * 512 + col)       = o0;
            *(float2*)(Om + (size_t)(row + 8) * 512 + col) = o1;
        }
    }
}

// ========== K3: per row: A = exp(softmax(s)), zero diagonal (in place) ==========
__global__ __launch_bounds__(256) void softmax_kernel()
{
    const int row = blockIdx.x;
    const int q = row & 511;
    float* r = g_A + (size_t)row * 512;
    const int tid = threadIdx.x;
    float v0 = r[tid], v1 = r[tid + 256];

    __shared__ float red[16];
    float m = fmaxf(v0, v1);
#pragma unroll
    for (int o = 16; o; o >>= 1) m = fmaxf(m, __shfl_xor_sync(0xffffffffu, m, o));
    if ((tid & 31) == 0) red[tid >> 5] = m;
    __syncthreads();
    m = fmaxf(fmaxf(fmaxf(red[0], red[1]), fmaxf(red[2], red[3])),
              fmaxf(fmaxf(red[4], red[5]), fmaxf(red[6], red[7])));

    float e0 = expf(v0 - m), e1 = expf(v1 - m);
    float s = e0 + e1;
#pragma unroll
    for (int o = 16; o; o >>= 1) s += __shfl_xor_sync(0xffffffffu, s, o);
    if ((tid & 31) == 0) red[8 + (tid >> 5)] = s;
    __syncthreads();
    s = ((red[8] + red[9]) + (red[10] + red[11])) +
        ((red[12] + red[13]) + (red[14] + red[15]));
    const float inv = 1.0f / s;

    float a0 = expf(e0 * inv); if (tid == q)       a0 = 0.f;
    float a1 = expf(e1 * inv); if (tid + 256 == q) a1 = 0.f;
    r[tid] = a0; r[tid + 256] = a1;
}

// ================= K4: f[bt][l] = x[b,l,:].Wroot[t,:] + broot[t] =================
__global__ __launch_bounds__(256) void f_kernel(const float* __restrict__ x,
                                                const float* __restrict__ Wroot,
                                                const float* __restrict__ broot)
{
    __shared__ float sW[T_ * H_];
    for (int idx = threadIdx.x; idx < T_ * H_; idx += 256) sW[idx] = Wroot[idx];
    __syncthreads();
    const int w = threadIdx.x >> 5, lane = threadIdx.x & 31;
    const int bl = blockIdx.x * 8 + w;
    const int b = bl >> 9, l = bl & 511;
    const float* xr = x + (size_t)bl * H_;
    float xv[24];
#pragma unroll
    for (int i = 0; i < 24; i++) xv[i] = xr[lane + i * 32];
#pragma unroll
    for (int t = 0; t < T_; t++) {
        float s = 0.f;
#pragma unroll
        for (int i = 0; i < 24; i++) s += xv[i] * sW[t * H_ + lane + i * 32];
#pragma unroll
        for (int o = 16; o; o >>= 1) s += __shfl_xor_sync(0xffffffffu, s, o);
        if (lane == 0) g_f[(b * T_ + t) * 512 + l] = s + broot[t];
    }
}

// ================= K5: deg[bt][k] = sum_q A[bt][q][k] =================
__global__ __launch_bounds__(512) void deg_kernel()
{
    const int bt = blockIdx.x, k = threadIdx.x;
    const float* Am = g_A + (size_t)bt * LL_ + k;
    float s0 = 0, s1 = 0, s2 = 0, s3 = 0;
    for (int q = 0; q < 512; q += 4) {
        s0 += Am[(size_t)q * 512];
        s1 += Am[(size_t)(q + 1) * 512];
        s2 += Am[(size_t)(q + 2) * 512];
        s3 += Am[(size_t)(q + 3) * 512];
    }
    g_deg[bt * 512 + k] = (s0 + s1) + (s2 + s3);
}

// ===== K6: permuted Lbar: W[i][j] = Lbar[(i+1)&511][(j+1)&511] =====
__global__ __launch_bounds__(512) void build_kernel()
{
    const int i = blockIdx.x, bt = blockIdx.y, j = threadIdx.x;
    const int pi = (i + 1) & 511, pj = (j + 1) & 511;
    float v;
    if (pi == 0) {
        v = g_f[bt * 512 + pj];
    } else {
        v = -g_A[(size_t)bt * LL_ + (size_t)pi * 512 + pj];
        if (pi == pj) v += g_deg[bt * 512 + pj];
    }
    g_W[(size_t)bt * LL_ + (size_t)i * 512 + j] = v;
}

// ===== K7: blocked Gauss-Jordan inverse (nb=64, no pivoting, all-fp32 FFMA2) =====
// Phase C double-buffered Ct + L2 prefetch of epilogue RMW lines.
// smem floats: sRP[64*512]=32768, sG[64*72]=4608, sCt0/sCt1[64*68]=4352 each,
//              sck[64], srk[64]
#define IV_RP  0
#define IV_G   32768
#define IV_CT0 (32768 + 4608)
#define IV_CT1 (32768 + 4608 + 4352)
#define IV_CK  (32768 + 4608 + 4352 + 4352)
#define IV_RK  (32768 + 4608 + 4352 + 4352 + 64)
#define SMEM_INV_FLOATS (32768 + 4608 + 4352 + 4352 + 128)
#define SMEM_INV_BYTES (SMEM_INV_FLOATS * 4)

__global__ __launch_bounds__(512) void invert_kernel()
{
    extern __shared__ float sm[];
    float* sRP  = sm + IV_RP;
    float* sG   = sm + IV_G;
    float* sCt0 = sm + IV_CT0;
    float* sCt1 = sm + IV_CT1;
    float* sck  = sm + IV_CK;
    float* srk  = sm + IV_RK;
    float* M = g_W + (size_t)blockIdx.x * LL_;
    const int tid = threadIdx.x;
    const int tx = tid & 63, ty = tid >> 6;
    const int c0 = tx * 4;
    const int ty8 = ty * 8;

    for (int s = 0; s < 8; s++) {
        const int k0 = s * 64;

        // ---- Phase A: load G = D^T, invert via GJ (G becomes (D^-1)^T) ----
        for (int idx = tid; idx < 4096; idx += 512) {
            int bb = idx >> 6, aa = idx & 63;
            sG[aa * 72 + bb] = M[(size_t)(k0 + bb) * 512 + k0 + aa];
        }
        __syncthreads();
        for (int k = 0; k < 64; k++) {
            if (tid < 64) { sck[tid] = sG[tid * 72 + k]; srk[tid] = sG[k * 72 + tid]; }
            __syncthreads();
            const float p = 1.0f / srk[k];
            for (int idx = tid; idx < 4096; idx += 512) {
                int i2 = idx >> 6, j2 = idx & 63;
                float v;
                if (i2 == k)      v = (j2 == k) ? p : srk[j2] * p;
                else if (j2 == k) v = -sck[i2] * p;
                else              v = sG[i2 * 72 + j2] - sck[i2] * (srk[j2] * p);
                sG[i2 * 72 + j2] = v;
            }
            __syncthreads();
        }

        // ---- Phase B: pivot rows S = Dinv*OldRows (FFMA2); write M + sRP ----
        {
            const int c = tid;
            const bool piv = (c >= k0) && (c < k0 + 64);
            const int cc = c - k0;
            unsigned long long acc2[32];
#pragma unroll
            for (int m = 0; m < 32; m++) acc2[m] = 0ull;
#pragma unroll 4
            for (int k = 0; k < 64; k++) {
                float rk = M[(size_t)(k0 + k) * 512 + c];
                unsigned long long ak = pk2(rk, rk);
                const ulonglong2* gp = (const ulonglong2*)&sG[k * 72];
#pragma unroll
                for (int m = 0; m < 16; m++) {
                    ulonglong2 g2 = gp[m];
                    FMA2(acc2[2 * m],     ak, g2.x);
                    FMA2(acc2[2 * m + 1], ak, g2.y);
                }
            }
#pragma unroll
            for (int m = 0; m < 32; m++) {
                float2 v = unpk(acc2[m]);
                int r0 = 2 * m, r1 = 2 * m + 1;
                float a0 = piv ? sG[cc * 72 + r0] : v.x;
                float a1 = piv ? sG[cc * 72 + r1] : v.y;
                sRP[r0 * 512 + c] = a0;
                sRP[r1 * 512 + c] = a1;
                M[(size_t)(k0 + r0) * 512 + c] = a0;
                M[(size_t)(k0 + r1) * 512 + c] = a1;
            }
        }
        __syncthreads();

        // ---- preload first rb's Ct into buffer 0 ----
        {
            const int rb0 = (s == 0) ? 1 : 0;
            const int nrow0 = rb0 * 64;
#pragma unroll
            for (int t = 0; t < 8; t++) {
                int idx = tid + t * 512;
                int rr = idx >> 6, k = idx & 63;
                sCt0[k * 68 + rr] = M[(size_t)(nrow0 + rr) * 512 + k0 + k];
            }
        }
        __syncthreads();

        // ---- Phase C: trailing update (FFMA2 8x8), double-buffered Ct ----
        int buf = 0;
        for (int ii = 0; ii < 7; ii++) {
            const int rb  = ii + (ii >= s ? 1 : 0);
            const int nn  = ii + 1;
            const int nxt = (nn < 7) ? (nn + (nn >= s ? 1 : 0)) : -1;
            const int row0 = rb * 64;
            float* sCtc = buf ? sCt1 : sCt0;
            float* sCtn = buf ? sCt0 : sCt1;

            // prefetch next rb's Ct into registers (hidden under compute)
            float pf[8];
            if (nxt >= 0) {
                const int nrow0 = nxt * 64;
#pragma unroll
                for (int t = 0; t < 8; t++) {
                    int idx = tid + t * 512;
                    int rr = idx >> 6, k = idx & 63;
                    pf[t] = M[(size_t)(nrow0 + rr) * 512 + k0 + k];
                }
            }
            // L2 prefetch of the epilogue RMW lines (one thread per 128B line)
            if ((tx & 7) == 0) {
#pragma unroll
                for (int i = 0; i < 8; i++) {
                    const float* p0 = &M[(size_t)(row0 + ty8 + i) * 512 + c0];
                    asm volatile("prefetch.global.L2 [%0];" :: "l"(p0));
                    asm volatile("prefetch.global.L2 [%0];" :: "l"(p0 + 256));
                }
            }

            unsigned long long acc2[8][4];
#pragma unroll
            for (int i = 0; i < 8; i++)
#pragma unroll
                for (int j = 0; j < 4; j++) acc2[i][j] = 0ull;

#pragma unroll 4
            for (int k = 0; k < 64; k++) {
                float a[8];
                *(float4*)(a)     = *(const float4*)&sCtc[k * 68 + ty8];
                *(float4*)(a + 4) = *(const float4*)&sCtc[k * 68 + ty8 + 4];
                ulonglong2 b0 = *(const ulonglong2*)&sRP[k * 512 + c0];
                ulonglong2 b1 = *(const ulonglong2*)&sRP[k * 512 + c0 + 256];
#pragma unroll
                for (int i = 0; i < 8; i++) {
                    unsigned long long aa = pk2(a[i], a[i]);
                    FMA2(acc2[i][0], aa, b0.x);
                    FMA2(acc2[i][1], aa, b0.y);
                    FMA2(acc2[i][2], aa, b1.x);
                    FMA2(acc2[i][3], aa, b1.y);
                }
            }

            const bool pivA = (c0 >= k0) && (c0 < k0 + 64);
            const bool pivB = (c0 + 256 >= k0) && (c0 + 256 < k0 + 64);
#pragma unroll
            for (int i = 0; i < 8; i++) {
                const int rr = ty8 + i;
                const int r = row0 + rr;
                float2 v0 = unpk(acc2[i][0]), v1 = unpk(acc2[i][1]);
                float2 v2 = unpk(acc2[i][2]), v3 = unpk(acc2[i][3]);
                float4 o0 = *(const float4*)&M[(size_t)r * 512 + c0];
                o0.x -= v0.x; o0.y -= v0.y; o0.z -= v1.x; o0.w -= v1.y;
                if (pivA) {
                    int cb = c0 - k0;
                    o0.x -= sCtc[(cb + 0) * 68 + rr];
                    o0.y -= sCtc[(cb + 1) * 68 + rr];
                    o0.z -= sCtc[(cb + 2) * 68 + rr];
                    o0.w -= sCtc[(cb + 3) * 68 + rr];
                }
                *(float4*)&M[(size_t)r * 512 + c0] = o0;
                float4 o1 = *(const float4*)&M[(size_t)r * 512 + c0 + 256];
                o1.x -= v2.x; o1.y -= v2.y; o1.z -= v3.x; o1.w -= v3.y;
                if (pivB) {
                    int cb = c0 + 256 - k0;
                    o1.x -= sCtc[(cb + 0) * 68 + rr];
                    o1.y -= sCtc[(cb + 1) * 68 + rr];
                    o1.z -= sCtc[(cb + 2) * 68 + rr];
                    o1.w -= sCtc[(cb + 3) * 68 + rr];
                }
                *(float4*)&M[(size_t)r * 512 + c0 + 256] = o1;
            }

            if (nxt >= 0) {
#pragma unroll
                for (int t = 0; t < 8; t++) {
                    int idx = tid + t * 512;
                    int rr = idx >> 6, k = idx & 63;
                    sCtn[k * 68 + rr] = pf[t];
                }
            }
            __syncthreads();
            buf ^= 1;
        }
    }
    g_diag[blockIdx.x * 512 + ((tid + 1) & 511)] = M[(size_t)tid * 512 + tid];
}

// ===== K8: att[i][j] = A[j][i] * ((i!=0)*diag[i] - (j!=0)*LLinv[i][j]) =====
__global__ __launch_bounds__(1024) void out_kernel(float* __restrict__ out)
{
    __shared__ float sA[32][33];
    const int bt = blockIdx.z;
    const int i0 = blockIdx.y * 32, j0 = blockIdx.x * 32;
    const int txx = threadIdx.x, tyy = threadIdx.y;
    const float* Abt = g_A + (size_t)bt * LL_;
    sA[tyy][txx] = Abt[(size_t)(j0 + tyy) * 512 + i0 + txx];
    __syncthreads();
    const int i = i0 + tyy, j = j0 + txx;
    const float Aji = sA[txx][tyy];
    const float ll = g_W[(size_t)bt * LL_ + (size_t)((i - 1) & 511) * 512 + ((j - 1) & 511)];
    const float dg = g_diag[bt * 512 + i];
    const float v = Aji * ((i ? dg : 0.f) - (j ? ll : 0.f));
    out[((size_t)bt * 512 + i) * 512 + j] = v;
}

extern "C" void kernel_launch(void* const* d_in, const int* in_sizes, int n_in,
                              void* d_out, int out_size)
{
    const float* X     = (const float*)d_in[0];
    const int*   mask  = (const int*)d_in[1];
    const float* Wq    = (const float*)d_in[2];
    const float* bq    = (const float*)d_in[3];
    const float* Wk    = (const float*)d_in[4];
    const float* bk    = (const float*)d_in[5];
    const float* Wroot = (const float*)d_in[6];
    const float* broot = (const float*)d_in[7];
    float* out = (float*)d_out;

    proj_kernel<<<dim3(6, 128, 2), 256>>>(X, Wq, bq, Wk, bk);
    scores_kernel<<<dim3(4, 4, 256), 256>>>(mask);
    softmax_kernel<<<BT_ * 512, 256>>>();
    f_kernel<<<2048, 256>>>(X, Wroot, broot);
    deg_kernel<<<BT_, 512>>>();
    build_kernel<<<dim3(512, BT_), 512>>>();
    cudaFuncSetAttribute(invert_kernel, cudaFuncAttributeMaxDynamicSharedMemorySize,
                         SMEM_INV_BYTES);
    invert_kernel<<<BT_, 512, SMEM_INV_BYTES>>>();
    out_kernel<<<dim3(16, 16, BT_), dim3(32, 32)>>>(out);
}